// round 12
// baseline (speedup 1.0000x reference)
#include <cuda_runtime.h>
#include <cuda_bf16.h>
#include <mma.h>
#include <cstdint>

using namespace nvcuda;

// Problem constants
#define BB 2
#define SS 2048
#define DD 1024
#define HH 16
#define DK 64
#define MT (BB*SS)      // 4096 token rows

// Scratch (device globals — no allocation allowed)
__device__ float g_Qh[BB*HH*SS*DK];   // [B,H,S,DK] tf32-rounded
__device__ float g_Kh[BB*HH*SS*DK];
__device__ float g_Vh[BB*HH*SS*DK];
__device__ float g_Ctx[BB*SS*DD];     // [B,S,D]  tf32-rounded
__device__ float g_Xr[3*MT*DD];       // rounded q,k,v
__device__ float g_Wr[4*DD*DD];       // rounded Wq,Wk,Wv,Wo

// ---------------------------------------------------------------------------
// helpers
// ---------------------------------------------------------------------------
__device__ __forceinline__ uint32_t smem_u32(const void* p) {
    uint32_t a;
    asm("{ .reg .u64 t; cvta.to.shared.u64 t, %1; cvt.u32.u64 %0, t; }"
        : "=r"(a) : "l"(p));
    return a;
}
__device__ __forceinline__ uint32_t f2tf32(float f) {          // round-to-nearest tf32
    uint32_t u;
    asm("cvt.rna.tf32.f32 %0, %1;" : "=r"(u) : "f"(f));
    return u;
}
__device__ __forceinline__ float rtf32(float f) { return __uint_as_float(f2tf32(f)); }

__device__ __forceinline__ void mma1688(float c[4], const uint32_t a[4],
                                        uint32_t b0, uint32_t b1) {
    asm volatile(
        "mma.sync.aligned.m16n8k8.row.col.f32.tf32.tf32.f32 "
        "{%0,%1,%2,%3}, {%4,%5,%6,%7}, {%8,%9}, {%0,%1,%2,%3};"
        : "+f"(c[0]), "+f"(c[1]), "+f"(c[2]), "+f"(c[3])
        : "r"(a[0]), "r"(a[1]), "r"(a[2]), "r"(a[3]), "r"(b0), "r"(b1));
}

#define CP_ASYNC16(saddr, gptr) \
    asm volatile("cp.async.cg.shared.global [%0], [%1], 16;" \
                 :: "r"((uint32_t)(saddr)), "l"(gptr))
#define CP_COMMIT() asm volatile("cp.async.commit_group;" ::: "memory")
#define CP_WAIT(n)  asm volatile("cp.async.wait_group %0;" :: "n"(n) : "memory")

// ---------------------------------------------------------------------------
// Pre-pass: RNA-round tensors to tf32 (kills truncation bias in HMMA)
// ---------------------------------------------------------------------------
__global__ void prep_round3(const float* __restrict__ a, const float* __restrict__ b,
                            const float* __restrict__ c, float* __restrict__ dst)
{
    const float* src = (blockIdx.z == 0) ? a : (blockIdx.z == 1) ? b : c;
    float* d = dst + (size_t)blockIdx.z * MT * DD;
    int i = blockIdx.x * 256 + threadIdx.x;        // float4 index, 1M total
    float4 v = *(const float4*)&src[i * 4];
    v.x = rtf32(v.x); v.y = rtf32(v.y); v.z = rtf32(v.z); v.w = rtf32(v.w);
    *(float4*)&d[i * 4] = v;
}
__global__ void prep_round4(const float* __restrict__ a, const float* __restrict__ b,
                            const float* __restrict__ c, const float* __restrict__ e,
                            float* __restrict__ dst)
{
    const float* src = (blockIdx.z == 0) ? a : (blockIdx.z == 1) ? b
                     : (blockIdx.z == 2) ? c : e;
    float* d = dst + (size_t)blockIdx.z * DD * DD;
    int i = blockIdx.x * 256 + threadIdx.x;        // float4 index, 256K total
    float4 v = *(const float4*)&src[i * 4];
    v.x = rtf32(v.x); v.y = rtf32(v.y); v.z = rtf32(v.z); v.w = rtf32(v.w);
    *(float4*)&d[i * 4] = v;
}

// ---------------------------------------------------------------------------
// wmma tf32 GEMM body: C[4096,1024] = A @ W + bias. A,W pre-rounded to tf32.
// 64x128 CTA tile, BK=32, 8 warps (2x4 warp grid of 32x32 warp tiles).
// Register-lean (acc=32 f/thread) -> 2 CTAs/SM without spills.
// MODE 0: row-major output (final, fp32).  MODE 1: head-split, tf32-rounded.
// ---------------------------------------------------------------------------
#define GBK 32
#define ALD 40    // A smem row stride (floats)
#define BLD 136   // B smem row stride (floats)
#define GA_STAGE (64*ALD)                    // 2560 floats
#define GB_STAGE (GBK*BLD)                   // 4352 floats
#define GSMEM_F  (2*GA_STAGE + 2*GB_STAGE)   // 13824 floats = 55296 B

template<int MODE>
__device__ __forceinline__ void gemm_body(
    const float* __restrict__ A, const float* __restrict__ B,
    const float* __restrict__ bias, float* __restrict__ C)
{
    extern __shared__ __align__(128) float sm[];
    float* As = sm;                    // [2][64][40]
    float* Bs = sm + 2 * GA_STAGE;     // [2][32][136]
    const uint32_t sAs = smem_u32(As);
    const uint32_t sBs = smem_u32(Bs);

    const int tid = threadIdx.x;
    const int w  = tid >> 5;
    const int wr = w >> 2;            // 0..1  -> rows 32*wr
    const int wc = w & 3;             // 0..3  -> cols 32*wc
    const int row0 = blockIdx.y * 64;
    const int col0 = blockIdx.x * 128;

    wmma::fragment<wmma::accumulator, 16, 16, 8, float> acc[2][2];
    #pragma unroll
    for (int i = 0; i < 2; i++)
        #pragma unroll
        for (int j = 0; j < 2; j++) wmma::fill_fragment(acc[i][j], 0.f);

    auto loadA = [&](int ks, int buf) {
        const float* Ag = A + (size_t)row0 * DD + ks * GBK;
        const uint32_t dst = sAs + buf * GA_STAGE * 4;
        #pragma unroll
        for (int u = 0; u < 2; u++) {
            int c = u * 256 + tid;             // 512 chunks
            int r = c >> 3, ch = c & 7;
            CP_ASYNC16(dst + r * (ALD*4) + ch * 16, Ag + (size_t)r * DD + ch * 4);
        }
    };
    auto loadB = [&](int ks, int buf) {
        const float* Bg = B + (size_t)(ks * GBK) * DD + col0;
        const uint32_t dst = sBs + buf * GB_STAGE * 4;
        #pragma unroll
        for (int u = 0; u < 4; u++) {
            int c = u * 256 + tid;             // 1024 chunks
            int r = c >> 5, ch = c & 31;
            CP_ASYNC16(dst + r * (BLD*4) + ch * 16, Bg + (size_t)r * DD + ch * 4);
        }
    };

    loadA(0, 0); loadB(0, 0); CP_COMMIT();

    const int NK = DD / GBK;          // 32
    for (int ks = 0; ks < NK; ks++) {
        if (ks + 1 < NK) {
            loadA(ks + 1, (ks + 1) & 1);
            loadB(ks + 1, (ks + 1) & 1);
            CP_COMMIT();
            CP_WAIT(1);
        } else {
            CP_WAIT(0);
        }
        __syncthreads();

        const float* Ab = As + (ks & 1) * GA_STAGE + wr * 32 * ALD;
        const float* Bb = Bs + (ks & 1) * GB_STAGE + wc * 32;
        #pragma unroll
        for (int kk = 0; kk < 4; kk++) {
            wmma::fragment<wmma::matrix_a, 16, 16, 8, wmma::precision::tf32,
                           wmma::row_major> fa[2];
            wmma::fragment<wmma::matrix_b, 16, 16, 8, wmma::precision::tf32,
                           wmma::row_major> fb[2];
            #pragma unroll
            for (int im = 0; im < 2; im++)
                wmma::load_matrix_sync(fa[im], Ab + im * 16 * ALD + kk * 8, ALD);
            #pragma unroll
            for (int in = 0; in < 2; in++)
                wmma::load_matrix_sync(fb[in], Bb + kk * 8 * BLD + in * 16, BLD);
            #pragma unroll
            for (int im = 0; im < 2; im++)
                #pragma unroll
                for (int in = 0; in < 2; in++)
                    wmma::mma_sync(acc[im][in], fa[im], fb[in], acc[im][in]);
        }
        __syncthreads();
    }

    // Epilogue: stage C in smem (reuse As/Bs space), ld = 136 (64x136 <= 13824 f)
    #pragma unroll
    for (int im = 0; im < 2; im++)
        #pragma unroll
        for (int in = 0; in < 2; in++)
            wmma::store_matrix_sync(&sm[(wr*32 + im*16) * 136 + wc*32 + in*16],
                                    acc[im][in], 136, wmma::mem_row_major);
    __syncthreads();

    #pragma unroll
    for (int u = 0; u < 8; u++) {
        int id = u * 256 + tid;                 // 2048 float4s
        int r  = id >> 5;
        int c4 = (id & 31) * 4;
        float4 vv = *(const float4*)&sm[r * 136 + c4];
        const int col = col0 + c4;
        vv.x += bias[col];  vv.y += bias[col+1];
        vv.z += bias[col+2]; vv.w += bias[col+3];
        const int trow = row0 + r;
        if (MODE == 0) {
            *(float4*)&C[(size_t)trow * DD + col] = vv;
        } else {
            vv.x = rtf32(vv.x); vv.y = rtf32(vv.y);
            vv.z = rtf32(vv.z); vv.w = rtf32(vv.w);
            const int b = trow >> 11;
            const int s = trow & (SS - 1);
            const int h = col >> 6;
            const int dk = col & (DK - 1);
            *(float4*)&C[(((size_t)(b*HH + h))*SS + s)*DK + dk] = vv;
        }
    }
}

// Merged QKV projection: grid (8, 64, 3); z selects input/weight/bias/output.
__global__ void __launch_bounds__(256, 2)
gemm_qkv(const float* __restrict__ Xr, const float* __restrict__ Wr,
         const float* __restrict__ bq, const float* __restrict__ bk,
         const float* __restrict__ bv,
         float* __restrict__ Qh, float* __restrict__ Kh, float* __restrict__ Vh)
{
    const int z = blockIdx.z;
    const float* A    = Xr + (size_t)z * MT * DD;
    const float* B    = Wr + (size_t)z * DD * DD;
    const float* bias = (z == 0) ? bq : (z == 1) ? bk : bv;
    float* C          = (z == 0) ? Qh : (z == 1) ? Kh : Vh;
    gemm_body<1>(A, B, bias, C);
}

// Final output projection
__global__ void __launch_bounds__(256, 2)
gemm_out(const float* __restrict__ Ctx, const float* __restrict__ Wr,
         const float* __restrict__ bo, float* __restrict__ C)
{
    gemm_body<0>(Ctx, Wr, bo, C);
}

// ---------------------------------------------------------------------------
// Flash attention with mma.sync tf32. CTA = (bh, 128-query tile), 8 warps,
// each warp owns 16 query rows. Q frags register-resident; K/V double-buffered
// cp.async; P round-trips through smem (layout change + tf32 rounding).
// Causal: tiles kt <= 2qt+1; per-element mask only when kt >= 2qt.
// ---------------------------------------------------------------------------
#define APAD 68
#define AT_SMEM_F (128*APAD + 4*64*APAD)    // Ps + 2xKs + 2xVs = 26112 floats

__global__ void __launch_bounds__(256)
attn_tc(const float* __restrict__ Qh, const float* __restrict__ Kh,
        const float* __restrict__ Vh, float* __restrict__ Ctx)
{
    extern __shared__ __align__(128) float sm[];
    float* Ps = sm;                         // [128][68]  (also Q staging)
    float* Ks = sm + 128*APAD;              // [2][64][68]
    float* Vs = Ks + 2*64*APAD;             // [2][64][68]
    const uint32_t sKs = smem_u32(Ks);
    const uint32_t sVs = smem_u32(Vs);

    const int bh = blockIdx.x;
    const int qt = (gridDim.y - 1) - blockIdx.y;    // big tiles first
    const int b  = bh >> 4;
    const int h  = bh & (HH - 1);

    const int tid  = threadIdx.x;
    const int w    = tid >> 5;
    const int lane = tid & 31;
    const int g    = lane >> 2;       // group id (row within fragment)
    const int t    = lane & 3;        // thread in group
    const int r0   = w * 16;          // warp's first local query row

    const float* Qp = Qh + (size_t)bh * SS * DK + (size_t)qt * 128 * DK;
    const float* Kp = Kh + (size_t)bh * SS * DK;
    const float* Vp = Vh + (size_t)bh * SS * DK;

    // stage Q tile 128x64 into Ps
    #pragma unroll
    for (int u = 0; u < 8; u++) {
        int c = u * 256 + tid;                 // 2048 float4 chunks
        int row = c >> 4, c4 = (c & 15) * 4;
        *(float4*)&Ps[row * APAD + c4] = *(const float4*)&Qp[(size_t)row * DK + c4];
    }
    __syncthreads();

    // Q fragments, scale folded in (log2 domain: 1/sqrt(64) * log2(e))
    const float SCL = 0.125f * 1.44269504088896f;
    uint32_t qf[8][4];
    #pragma unroll
    for (int ks = 0; ks < 8; ks++) {
        int k0 = ks * 8;
        qf[ks][0] = f2tf32(Ps[(r0+g  )*APAD + k0 + t    ] * SCL);
        qf[ks][1] = f2tf32(Ps[(r0+g+8)*APAD + k0 + t    ] * SCL);
        qf[ks][2] = f2tf32(Ps[(r0+g  )*APAD + k0 + t + 4] * SCL);
        qf[ks][3] = f2tf32(Ps[(r0+g+8)*APAD + k0 + t + 4] * SCL);
    }
    __syncthreads();

    float m0 = -1e30f, m1 = -1e30f, l0 = 0.f, l1 = 0.f;
    float Oa[8][4];
    #pragma unroll
    for (int f = 0; f < 8; f++)
        #pragma unroll
        for (int r = 0; r < 4; r++) Oa[f][r] = 0.f;

    const int ktmax = 2 * qt + 1;

    // K/V tile loader (64x64 each) into buffer `buf`
    auto load_kv = [&](int kt, int buf) {
        const uint32_t dK = sKs + buf * (64*APAD*4);
        const uint32_t dV = sVs + buf * (64*APAD*4);
        #pragma unroll
        for (int u = 0; u < 4; u++) {
            int c = u * 256 + tid;            // 1024 chunks each
            int row = c >> 4, ch = c & 15;
            CP_ASYNC16(dK + row*(APAD*4) + ch*16,
                       Kp + (size_t)(kt*64 + row)*DK + ch*4);
            CP_ASYNC16(dV + row*(APAD*4) + ch*16,
                       Vp + (size_t)(kt*64 + row)*DK + ch*4);
        }
        CP_COMMIT();
    };

    load_kv(0, 0);

    for (int kt = 0; kt <= ktmax; kt++) {
        CP_WAIT(0);
        __syncthreads();
        if (kt + 1 <= ktmax) load_kv(kt + 1, (kt + 1) & 1);

        const float* Kb = Ks + (kt & 1) * 64 * APAD;
        const float* Vb = Vs + (kt & 1) * 64 * APAD;

        // S = (Q*scl) @ K^T    (Sa[f]: 16 rows x 8 keys, f = key octet)
        float Sa[8][4];
        #pragma unroll
        for (int f = 0; f < 8; f++)
            #pragma unroll
            for (int r = 0; r < 4; r++) Sa[f][r] = 0.f;
        #pragma unroll
        for (int ks = 0; ks < 8; ks++) {
            int k0 = ks * 8;
            #pragma unroll
            for (int f = 0; f < 8; f++) {
                uint32_t b0 = __float_as_uint(Kb[(f*8 + g)*APAD + k0 + t    ]);
                uint32_t b1 = __float_as_uint(Kb[(f*8 + g)*APAD + k0 + t + 4]);
                mma1688(Sa[f], qf[ks], b0, b1);
            }
        }

        // causal mask (only near/on diagonal)
        if (kt >= 2 * qt) {
            const int grow0 = qt*128 + r0 + g;
            const int grow1 = grow0 + 8;
            #pragma unroll
            for (int f = 0; f < 8; f++) {
                const int c0 = kt*64 + f*8 + 2*t;
                if (c0     > grow0) Sa[f][0] = -1e30f;
                if (c0 + 1 > grow0) Sa[f][1] = -1e30f;
                if (c0     > grow1) Sa[f][2] = -1e30f;
                if (c0 + 1 > grow1) Sa[f][3] = -1e30f;
            }
        }

        // online softmax (log2 domain)
        float mx0 = -1e30f, mx1 = -1e30f;
        #pragma unroll
        for (int f = 0; f < 8; f++) {
            mx0 = fmaxf(mx0, fmaxf(Sa[f][0], Sa[f][1]));
            mx1 = fmaxf(mx1, fmaxf(Sa[f][2], Sa[f][3]));
        }
        mx0 = fmaxf(mx0, __shfl_xor_sync(0xffffffffu, mx0, 1));
        mx0 = fmaxf(mx0, __shfl_xor_sync(0xffffffffu, mx0, 2));
        mx1 = fmaxf(mx1, __shfl_xor_sync(0xffffffffu, mx1, 1));
        mx1 = fmaxf(mx1, __shfl_xor_sync(0xffffffffu, mx1, 2));

        const float mn0 = fmaxf(m0, mx0), mn1 = fmaxf(m1, mx1);
        const float corr0 = exp2f(m0 - mn0), corr1 = exp2f(m1 - mn1);
        float s0 = 0.f, s1 = 0.f;
        #pragma unroll
        for (int f = 0; f < 8; f++) {
            float p00 = exp2f(Sa[f][0] - mn0);
            float p01 = exp2f(Sa[f][1] - mn0);
            float p10 = exp2f(Sa[f][2] - mn1);
            float p11 = exp2f(Sa[f][3] - mn1);
            s0 += p00 + p01;  s1 += p10 + p11;
            float2 v0 = make_float2(rtf32(p00), rtf32(p01));
            float2 v1 = make_float2(rtf32(p10), rtf32(p11));
            *(float2*)&Ps[(r0+g  )*APAD + f*8 + 2*t] = v0;
            *(float2*)&Ps[(r0+g+8)*APAD + f*8 + 2*t] = v1;
        }
        s0 += __shfl_xor_sync(0xffffffffu, s0, 1);
        s0 += __shfl_xor_sync(0xffffffffu, s0, 2);
        s1 += __shfl_xor_sync(0xffffffffu, s1, 1);
        s1 += __shfl_xor_sync(0xffffffffu, s1, 2);
        l0 = l0 * corr0 + s0;  m0 = mn0;
        l1 = l1 * corr1 + s1;  m1 = mn1;

        #pragma unroll
        for (int f = 0; f < 8; f++) {
            Oa[f][0] *= corr0; Oa[f][1] *= corr0;
            Oa[f][2] *= corr1; Oa[f][3] *= corr1;
        }
        __syncwarp();

        // O += P @ V   (A = P from smem, B = V)
        #pragma unroll
        for (int ks = 0; ks < 8; ks++) {
            int k0 = ks * 8;
            uint32_t pa[4];
            pa[0] = __float_as_uint(Ps[(r0+g  )*APAD + k0 + t    ]);
            pa[1] = __float_as_uint(Ps[(r0+g+8)*APAD + k0 + t    ]);
            pa[2] = __float_as_uint(Ps[(r0+g  )*APAD + k0 + t + 4]);
            pa[3] = __float_as_uint(Ps[(r0+g+8)*APAD + k0 + t + 4]);
            #pragma unroll
            for (int f = 0; f < 8; f++) {
                uint32_t b0 = __float_as_uint(Vb[(k0 + t    )*APAD + f*8 + g]);
                uint32_t b1 = __float_as_uint(Vb[(k0 + t + 4)*APAD + f*8 + g]);
                mma1688(Oa[f], pa, b0, b1);
            }
        }
        __syncthreads();
    }

    // normalize + write Ctx [B,S,D], tf32-rounded (feeds final GEMM)
    const float inv0 = 1.f / l0, inv1 = 1.f / l1;
    const int srow0 = qt*128 + r0 + g;
    const int srow1 = srow0 + 8;
    #pragma unroll
    for (int f = 0; f < 8; f++) {
        const int col = h*64 + f*8 + 2*t;
        float2 v0 = make_float2(rtf32(Oa[f][0]*inv0), rtf32(Oa[f][1]*inv0));
        float2 v1 = make_float2(rtf32(Oa[f][2]*inv1), rtf32(Oa[f][3]*inv1));
        *(float2*)&Ctx[((size_t)(b*SS + srow0))*DD + col] = v0;
        *(float2*)&Ctx[((size_t)(b*SS + srow1))*DD + col] = v1;
    }
}

// ---------------------------------------------------------------------------
extern "C" void kernel_launch(void* const* d_in, const int* in_sizes, int n_in,
                              void* d_out, int out_size)
{
    const float* q  = (const float*)d_in[0];
    const float* k  = (const float*)d_in[1];
    const float* v  = (const float*)d_in[2];
    // d_in[3] = mask (strict causal tril) — implemented analytically
    const float* Wq = (const float*)d_in[4];
    const float* bq = (const float*)d_in[5];
    const float* Wk = (const float*)d_in[6];
    const float* bk = (const float*)d_in[7];
    const float* Wv = (const float*)d_in[8];
    const float* bv = (const float*)d_in[9];
    const float* Wo = (const float*)d_in[10];
    const float* bo = (const float*)d_in[11];
    float* out = (float*)d_out;

    float *pQh, *pKh, *pVh, *pCtx, *pXr, *pWr;
    cudaGetSymbolAddress((void**)&pQh,  g_Qh);
    cudaGetSymbolAddress((void**)&pKh,  g_Kh);
    cudaGetSymbolAddress((void**)&pVh,  g_Vh);
    cudaGetSymbolAddress((void**)&pCtx, g_Ctx);
    cudaGetSymbolAddress((void**)&pXr,  g_Xr);
    cudaGetSymbolAddress((void**)&pWr,  g_Wr);

    const int gemm_smem = GSMEM_F * 4;          // 55296 B
    const int attn_smem = AT_SMEM_F * 4;        // 104448 B
    cudaFuncSetAttribute(gemm_qkv, cudaFuncAttributeMaxDynamicSharedMemorySize, gemm_smem);
    cudaFuncSetAttribute(gemm_out, cudaFuncAttributeMaxDynamicSharedMemorySize, gemm_smem);
    cudaFuncSetAttribute(attn_tc,  cudaFuncAttributeMaxDynamicSharedMemorySize, attn_smem);

    // pre-round inputs to tf32 (RNA)
    prep_round3<<<dim3(MT*DD/(4*256), 1, 3), 256>>>(q, k, v, pXr);
    prep_round4<<<dim3(DD*DD/(4*256), 1, 4), 256>>>(Wq, Wk, Wv, Wo, pWr);

    // merged QKV projection: one launch, 1536 CTAs
    gemm_qkv<<<dim3(DD/128, MT/64, 3), 256, gemm_smem>>>(
        pXr, pWr, bq, bk, bv, pQh, pKh, pVh);

    dim3 gAttn(BB*HH, SS/128);    // (32, 16), qt reversed inside
    attn_tc<<<gAttn, 256, attn_smem>>>(pQh, pKh, pVh, pCtx);

    gemm_out<<<dim3(DD/128, MT/64), 256, gemm_smem>>>(pCtx, pWr + 3*DD*DD, bo, out);
}

// round 13
// speedup vs baseline: 3.1388x; 3.1388x over previous
#include <cuda_runtime.h>
#include <cuda_fp16.h>
#include <mma.h>
#include <cstdint>

using namespace nvcuda;

// Problem constants
#define BB 2
#define SS 2048
#define DD 1024
#define HH 16
#define DK 64
#define MT (BB*SS)      // 4096 token rows

// Scratch (device globals — no allocation allowed)
__device__ __half g_Xh[3*MT*DD];        // fp16 q,k,v inputs
__device__ __half g_Wh[4*DD*DD];        // fp16 weights
__device__ __half g_Qh[BB*HH*SS*DK];    // [B,H,S,DK]
__device__ __half g_Kh[BB*HH*SS*DK];
__device__ __half g_Vh[BB*HH*SS*DK];
__device__ __half g_Vt[BB*HH*DK*SS];    // [B,H,DK,S] transposed V
__device__ __half g_Ctx[BB*SS*DD];      // [B,S,D]

// ---------------------------------------------------------------------------
// helpers
// ---------------------------------------------------------------------------
__device__ __forceinline__ uint32_t smem_u32(const void* p) {
    uint32_t a;
    asm("{ .reg .u64 t; cvta.to.shared.u64 t, %1; cvt.u32.u64 %0, t; }"
        : "=r"(a) : "l"(p));
    return a;
}

__device__ __forceinline__ void mma16816(float c[4], const uint32_t a[4],
                                         uint32_t b0, uint32_t b1) {
    asm volatile(
        "mma.sync.aligned.m16n8k16.row.col.f32.f16.f16.f32 "
        "{%0,%1,%2,%3}, {%4,%5,%6,%7}, {%8,%9}, {%0,%1,%2,%3};"
        : "+f"(c[0]), "+f"(c[1]), "+f"(c[2]), "+f"(c[3])
        : "r"(a[0]), "r"(a[1]), "r"(a[2]), "r"(a[3]), "r"(b0), "r"(b1));
}

#define CP_ASYNC16(saddr, gptr) \
    asm volatile("cp.async.cg.shared.global [%0], [%1], 16;" \
                 :: "r"((uint32_t)(saddr)), "l"(gptr))
#define CP_COMMIT() asm volatile("cp.async.commit_group;" ::: "memory")
#define CP_WAIT(n)  asm volatile("cp.async.wait_group %0;" :: "n"(n) : "memory")

// ---------------------------------------------------------------------------
// Pre-pass: convert fp32 tensors to fp16 (RNE)
// ---------------------------------------------------------------------------
__global__ void prep_half3(const float* __restrict__ a, const float* __restrict__ b,
                           const float* __restrict__ c, __half* __restrict__ dst)
{
    const float* src = (blockIdx.z == 0) ? a : (blockIdx.z == 1) ? b : c;
    __half* d = dst + (size_t)blockIdx.z * MT * DD;
    int i = blockIdx.x * 256 + threadIdx.x;        // 4-float chunk index
    float4 v = *(const float4*)&src[(size_t)i * 4];
    *(__half2*)&d[(size_t)i*4 + 0] = __floats2half2_rn(v.x, v.y);
    *(__half2*)&d[(size_t)i*4 + 2] = __floats2half2_rn(v.z, v.w);
}
__global__ void prep_half4(const float* __restrict__ a, const float* __restrict__ b,
                           const float* __restrict__ c, const float* __restrict__ e,
                           __half* __restrict__ dst)
{
    const float* src = (blockIdx.z == 0) ? a : (blockIdx.z == 1) ? b
                     : (blockIdx.z == 2) ? c : e;
    __half* d = dst + (size_t)blockIdx.z * DD * DD;
    int i = blockIdx.x * 256 + threadIdx.x;
    float4 v = *(const float4*)&src[(size_t)i * 4];
    *(__half2*)&d[(size_t)i*4 + 0] = __floats2half2_rn(v.x, v.y);
    *(__half2*)&d[(size_t)i*4 + 2] = __floats2half2_rn(v.z, v.w);
}

// ---------------------------------------------------------------------------
// V transpose: Vh [B,H,S,DK] -> Vt [B,H,DK,S], fp16, 64x64 tiles
// ---------------------------------------------------------------------------
__global__ void transpose_v(const __half* __restrict__ Vh, __half* __restrict__ Vt)
{
    __shared__ __half tl[64][72];
    const int bh = blockIdx.y;
    const int st = blockIdx.x;           // s-tile (32)
    const __half* src = Vh + (size_t)bh * SS * DK + (size_t)st * 64 * DK;
    __half* dst = Vt + (size_t)bh * DK * SS + st * 64;
    const int tid = threadIdx.x;
    #pragma unroll
    for (int u = 0; u < 2; u++) {
        int c = u * 256 + tid;           // 512 chunks of 8 halfs
        int r = c >> 3, ch = c & 7;
        *(uint4*)&tl[r][ch * 8] = *(const uint4*)&src[(size_t)r * DK + ch * 8];
    }
    __syncthreads();
    #pragma unroll
    for (int u = 0; u < 8; u++) {
        int i = u * 256 + tid;           // 2048 half2 writes
        int dk = i >> 5, sp = (i & 31) * 2;
        __half2 h = __halves2half2(tl[sp][dk], tl[sp + 1][dk]);
        *(__half2*)&dst[(size_t)dk * SS + sp] = h;
    }
}

// ---------------------------------------------------------------------------
// wmma fp16 GEMM body: C[4096,1024] = A @ W + bias. A,W fp16, acc fp32.
// 128x128 CTA tile, BK=32, 8 warps (4x2 warp grid, 32x64 warp tiles).
// MODE 0: fp32 row-major output.  MODE 1: fp16 head-split [B,H,S,DK].
// ---------------------------------------------------------------------------
#define GBK 32
#define ALD 40    // A smem row stride (halfs)
#define BLD 136   // B smem row stride (halfs)
#define GA_STAGE (128*ALD)                       // halfs
#define GB_STAGE (GBK*BLD)                       // halfs
#define GSMEM_B  ((2*GA_STAGE + 2*GB_STAGE)*2)   // 37888 bytes

template<int MODE>
__device__ __forceinline__ void gemm_body(
    const __half* __restrict__ A, const __half* __restrict__ B,
    const float* __restrict__ bias, void* __restrict__ C)
{
    extern __shared__ __align__(128) __half smh[];
    __half* As = smh;                      // [2][128][40]
    __half* Bs = smh + 2 * GA_STAGE;       // [2][32][136]
    float* smf = (float*)smh;              // epilogue staging (64x136 fp32)
    const uint32_t sAs = smem_u32(As);
    const uint32_t sBs = smem_u32(Bs);

    const int tid = threadIdx.x;
    const int w  = tid >> 5;
    const int wr = w >> 1;            // 0..3 -> rows 32*wr
    const int wc = w & 1;             // 0..1 -> cols 64*wc
    const int row0 = blockIdx.y * 128;
    const int col0 = blockIdx.x * 128;

    wmma::fragment<wmma::accumulator, 16, 16, 16, float> acc[2][4];
    #pragma unroll
    for (int i = 0; i < 2; i++)
        #pragma unroll
        for (int j = 0; j < 4; j++) wmma::fill_fragment(acc[i][j], 0.f);

    auto loadA = [&](int ks, int buf) {
        const __half* Ag = A + (size_t)row0 * DD + ks * GBK;
        const uint32_t dst = sAs + buf * GA_STAGE * 2;
        #pragma unroll
        for (int u = 0; u < 2; u++) {
            int c = u * 256 + tid;             // 512 chunks of 8 halfs
            int r = c >> 2, ch = c & 3;
            CP_ASYNC16(dst + r * (ALD*2) + ch * 16, Ag + (size_t)r * DD + ch * 8);
        }
    };
    auto loadB = [&](int ks, int buf) {
        const __half* Bg = B + (size_t)(ks * GBK) * DD + col0;
        const uint32_t dst = sBs + buf * GB_STAGE * 2;
        #pragma unroll
        for (int u = 0; u < 2; u++) {
            int c = u * 256 + tid;             // 512 chunks
            int r = c >> 4, ch = c & 15;
            CP_ASYNC16(dst + r * (BLD*2) + ch * 16, Bg + (size_t)r * DD + ch * 8);
        }
    };

    loadA(0, 0); loadB(0, 0); CP_COMMIT();

    const int NK = DD / GBK;          // 32
    for (int ks = 0; ks < NK; ks++) {
        if (ks + 1 < NK) {
            loadA(ks + 1, (ks + 1) & 1);
            loadB(ks + 1, (ks + 1) & 1);
            CP_COMMIT();
            CP_WAIT(1);
        } else {
            CP_WAIT(0);
        }
        __syncthreads();

        const __half* Ab = As + (ks & 1) * GA_STAGE + wr * 32 * ALD;
        const __half* Bb = Bs + (ks & 1) * GB_STAGE + wc * 64;
        #pragma unroll
        for (int kk = 0; kk < 2; kk++) {      // BK/16
            wmma::fragment<wmma::matrix_a, 16, 16, 16, __half, wmma::row_major> fa[2];
            wmma::fragment<wmma::matrix_b, 16, 16, 16, __half, wmma::row_major> fb[4];
            #pragma unroll
            for (int im = 0; im < 2; im++)
                wmma::load_matrix_sync(fa[im], Ab + im * 16 * ALD + kk * 16, ALD);
            #pragma unroll
            for (int in = 0; in < 4; in++)
                wmma::load_matrix_sync(fb[in], Bb + kk * 16 * BLD + in * 16, BLD);
            #pragma unroll
            for (int im = 0; im < 2; im++)
                #pragma unroll
                for (int in = 0; in < 4; in++)
                    wmma::mma_sync(acc[im][in], fa[im], fb[in], acc[im][in]);
        }
        __syncthreads();
    }

    // Epilogue: two passes of 64 rows through fp32 smem staging (ld=136)
    #pragma unroll
    for (int p = 0; p < 2; p++) {
        if (wr >= p * 2 && wr < p * 2 + 2) {
            const int lr = (wr - p * 2) * 32;
            #pragma unroll
            for (int im = 0; im < 2; im++)
                #pragma unroll
                for (int in = 0; in < 4; in++)
                    wmma::store_matrix_sync(&smf[(lr + im*16) * 136 + wc*64 + in*16],
                                            acc[im][in], 136, wmma::mem_row_major);
        }
        __syncthreads();

        #pragma unroll
        for (int u = 0; u < 8; u++) {
            int id = u * 256 + tid;                 // 2048 float4s
            int r  = id >> 5;
            int c4 = (id & 31) * 4;
            float4 vv = *(const float4*)&smf[r * 136 + c4];
            const int col = col0 + c4;
            vv.x += bias[col];   vv.y += bias[col+1];
            vv.z += bias[col+2]; vv.w += bias[col+3];
            const int trow = row0 + p * 64 + r;
            if (MODE == 0) {
                *(float4*)&((float*)C)[(size_t)trow * DD + col] = vv;
            } else {
                const int b = trow >> 11;
                const int s = trow & (SS - 1);
                const int h = col >> 6;
                const int dk = col & (DK - 1);
                __half* dst = (__half*)C + (((size_t)(b*HH + h))*SS + s)*DK + dk;
                *(__half2*)&dst[0] = __floats2half2_rn(vv.x, vv.y);
                *(__half2*)&dst[2] = __floats2half2_rn(vv.z, vv.w);
            }
        }
        __syncthreads();
    }
}

// Merged QKV projection: grid (8, 32, 3)
__global__ void __launch_bounds__(256)
gemm_qkv(const __half* __restrict__ Xh, const __half* __restrict__ Wh,
         const float* __restrict__ bq, const float* __restrict__ bk,
         const float* __restrict__ bv,
         __half* __restrict__ Qh, __half* __restrict__ Kh, __half* __restrict__ Vh)
{
    const int z = blockIdx.z;
    const __half* A    = Xh + (size_t)z * MT * DD;
    const __half* B    = Wh + (size_t)z * DD * DD;
    const float* bias  = (z == 0) ? bq : (z == 1) ? bk : bv;
    __half* C          = (z == 0) ? Qh : (z == 1) ? Kh : Vh;
    gemm_body<1>(A, B, bias, C);
}

__global__ void __launch_bounds__(256)
gemm_out(const __half* __restrict__ Ctx, const __half* __restrict__ Wh,
         const float* __restrict__ bo, float* __restrict__ C)
{
    gemm_body<0>(Ctx, Wh, bo, C);
}

// ---------------------------------------------------------------------------
// Flash attention, fp16 mma m16n8k16. CTA = (bh, 128-query tile), 8 warps,
// each warp 16 query rows. Q frags from global; K [key][dk], V^T [dk][key]
// fp16 smem double-buffered; P fp16 in smem. Scale applied on fp32 S.
// ---------------------------------------------------------------------------
#define HPAD 72
#define AT_PS   (128*HPAD)                 // halfs
#define AT_KS   (2*64*HPAD)
#define AT_SMEM_B ((AT_PS + 2*AT_KS)*2)    // 55296 bytes

__global__ void __launch_bounds__(256, 2)
attn_tc(const __half* __restrict__ Qh, const __half* __restrict__ Kh,
        const __half* __restrict__ Vt, __half* __restrict__ Ctx)
{
    extern __shared__ __align__(128) __half smh[];
    __half* Ps = smh;                       // [128][72]
    __half* Ks = smh + AT_PS;               // [2][64][72]  (key-major)
    __half* Vs = Ks + AT_KS;                // [2][64][72]  (dk-major: V^T)
    const uint32_t sKs = smem_u32(Ks);
    const uint32_t sVs = smem_u32(Vs);

    const int bh = blockIdx.x;
    const int qt = (gridDim.y - 1) - blockIdx.y;    // big tiles first
    const int b  = bh >> 4;
    const int h  = bh & (HH - 1);

    const int tid  = threadIdx.x;
    const int w    = tid >> 5;
    const int lane = tid & 31;
    const int g    = lane >> 2;
    const int t    = lane & 3;
    const int r0   = w * 16;

    const __half* Qp = Qh + (size_t)bh * SS * DK + (size_t)qt * 128 * DK;
    const __half* Kp = Kh + (size_t)bh * SS * DK;
    const __half* Vp = Vt + (size_t)bh * DK * SS;

    // Q fragments straight from global (fp16 pairs)
    uint32_t qf[4][4];
    #pragma unroll
    for (int ks = 0; ks < 4; ks++) {
        const int k0 = ks * 16;
        qf[ks][0] = *(const uint32_t*)&Qp[(size_t)(r0+g  )*DK + k0 + 2*t    ];
        qf[ks][1] = *(const uint32_t*)&Qp[(size_t)(r0+g+8)*DK + k0 + 2*t    ];
        qf[ks][2] = *(const uint32_t*)&Qp[(size_t)(r0+g  )*DK + k0 + 2*t + 8];
        qf[ks][3] = *(const uint32_t*)&Qp[(size_t)(r0+g+8)*DK + k0 + 2*t + 8];
    }

    float m0 = -1e30f, m1 = -1e30f, l0 = 0.f, l1 = 0.f;
    float Oa[8][4];
    #pragma unroll
    for (int f = 0; f < 8; f++)
        #pragma unroll
        for (int r = 0; r < 4; r++) Oa[f][r] = 0.f;

    const int ktmax = 2 * qt + 1;
    const float SCL = 0.125f * 1.44269504088896f;   // 1/sqrt(dk) * log2(e)

    // K tile [64 keys][64 dk], V^T tile [64 dk][64 keys]
    auto load_kv = [&](int kt, int buf) {
        const uint32_t dK = sKs + buf * (64*HPAD*2);
        const uint32_t dV = sVs + buf * (64*HPAD*2);
        #pragma unroll
        for (int u = 0; u < 2; u++) {
            int c = u * 256 + tid;            // 512 chunks each of 8 halfs
            int row = c >> 3, ch = c & 7;
            CP_ASYNC16(dK + row*(HPAD*2) + ch*16,
                       Kp + (size_t)(kt*64 + row)*DK + ch*8);
            CP_ASYNC16(dV + row*(HPAD*2) + ch*16,
                       Vp + (size_t)row*SS + kt*64 + ch*8);
        }
        CP_COMMIT();
    };

    load_kv(0, 0);

    for (int kt = 0; kt <= ktmax; kt++) {
        CP_WAIT(0);
        __syncthreads();
        if (kt + 1 <= ktmax) load_kv(kt + 1, (kt + 1) & 1);

        const __half* Kb = Ks + (kt & 1) * 64 * HPAD;
        const __half* Vb = Vs + (kt & 1) * 64 * HPAD;

        // S = Q @ K^T
        float Sa[8][4];
        #pragma unroll
        for (int f = 0; f < 8; f++)
            #pragma unroll
            for (int r = 0; r < 4; r++) Sa[f][r] = 0.f;
        #pragma unroll
        for (int ks = 0; ks < 4; ks++) {
            const int k0 = ks * 16;
            #pragma unroll
            for (int f = 0; f < 8; f++) {
                uint32_t b0 = *(const uint32_t*)&Kb[(f*8+g)*HPAD + k0 + 2*t    ];
                uint32_t b1 = *(const uint32_t*)&Kb[(f*8+g)*HPAD + k0 + 2*t + 8];
                mma16816(Sa[f], qf[ks], b0, b1);
            }
        }
        // scale (fp32, exact)
        #pragma unroll
        for (int f = 0; f < 8; f++) {
            Sa[f][0] *= SCL; Sa[f][1] *= SCL; Sa[f][2] *= SCL; Sa[f][3] *= SCL;
        }

        // causal mask (near/on diagonal only)
        if (kt >= 2 * qt) {
            const int grow0 = qt*128 + r0 + g;
            const int grow1 = grow0 + 8;
            #pragma unroll
            for (int f = 0; f < 8; f++) {
                const int c0 = kt*64 + f*8 + 2*t;
                if (c0     > grow0) Sa[f][0] = -1e30f;
                if (c0 + 1 > grow0) Sa[f][1] = -1e30f;
                if (c0     > grow1) Sa[f][2] = -1e30f;
                if (c0 + 1 > grow1) Sa[f][3] = -1e30f;
            }
        }

        // online softmax (log2 domain)
        float mx0 = -1e30f, mx1 = -1e30f;
        #pragma unroll
        for (int f = 0; f < 8; f++) {
            mx0 = fmaxf(mx0, fmaxf(Sa[f][0], Sa[f][1]));
            mx1 = fmaxf(mx1, fmaxf(Sa[f][2], Sa[f][3]));
        }
        mx0 = fmaxf(mx0, __shfl_xor_sync(0xffffffffu, mx0, 1));
        mx0 = fmaxf(mx0, __shfl_xor_sync(0xffffffffu, mx0, 2));
        mx1 = fmaxf(mx1, __shfl_xor_sync(0xffffffffu, mx1, 1));
        mx1 = fmaxf(mx1, __shfl_xor_sync(0xffffffffu, mx1, 2));

        const float mn0 = fmaxf(m0, mx0), mn1 = fmaxf(m1, mx1);
        const float corr0 = exp2f(m0 - mn0), corr1 = exp2f(m1 - mn1);
        float s0 = 0.f, s1 = 0.f;
        #pragma unroll
        for (int f = 0; f < 8; f++) {
            float p00 = exp2f(Sa[f][0] - mn0);
            float p01 = exp2f(Sa[f][1] - mn0);
            float p10 = exp2f(Sa[f][2] - mn1);
            float p11 = exp2f(Sa[f][3] - mn1);
            s0 += p00 + p01;  s1 += p10 + p11;
            *(__half2*)&Ps[(r0+g  )*HPAD + f*8 + 2*t] = __floats2half2_rn(p00, p01);
            *(__half2*)&Ps[(r0+g+8)*HPAD + f*8 + 2*t] = __floats2half2_rn(p10, p11);
        }
        s0 += __shfl_xor_sync(0xffffffffu, s0, 1);
        s0 += __shfl_xor_sync(0xffffffffu, s0, 2);
        s1 += __shfl_xor_sync(0xffffffffu, s1, 1);
        s1 += __shfl_xor_sync(0xffffffffu, s1, 2);
        l0 = l0 * corr0 + s0;  m0 = mn0;
        l1 = l1 * corr1 + s1;  m1 = mn1;

        #pragma unroll
        for (int f = 0; f < 8; f++) {
            Oa[f][0] *= corr0; Oa[f][1] *= corr0;
            Oa[f][2] *= corr1; Oa[f][3] *= corr1;
        }
        __syncwarp();

        // O += P @ V   (A = P [row][key], B = V^T [dk][key])
        #pragma unroll
        for (int ks = 0; ks < 4; ks++) {
            const int k0 = ks * 16;
            uint32_t pa[4];
            pa[0] = *(const uint32_t*)&Ps[(r0+g  )*HPAD + k0 + 2*t    ];
            pa[1] = *(const uint32_t*)&Ps[(r0+g+8)*HPAD + k0 + 2*t    ];
            pa[2] = *(const uint32_t*)&Ps[(r0+g  )*HPAD + k0 + 2*t + 8];
            pa[3] = *(const uint32_t*)&Ps[(r0+g+8)*HPAD + k0 + 2*t + 8];
            #pragma unroll
            for (int f = 0; f < 8; f++) {
                uint32_t b0 = *(const uint32_t*)&Vb[(f*8+g)*HPAD + k0 + 2*t    ];
                uint32_t b1 = *(const uint32_t*)&Vb[(f*8+g)*HPAD + k0 + 2*t + 8];
                mma16816(Oa[f], pa, b0, b1);
            }
        }
        __syncthreads();
    }

    // normalize + write Ctx [B,S,D] fp16 (feeds final GEMM)
    const float inv0 = 1.f / l0, inv1 = 1.f / l1;
    const int srow0 = qt*128 + r0 + g;
    const int srow1 = srow0 + 8;
    #pragma unroll
    for (int f = 0; f < 8; f++) {
        const int col = h*64 + f*8 + 2*t;
        *(__half2*)&Ctx[((size_t)(b*SS + srow0))*DD + col] =
            __floats2half2_rn(Oa[f][0]*inv0, Oa[f][1]*inv0);
        *(__half2*)&Ctx[((size_t)(b*SS + srow1))*DD + col] =
            __floats2half2_rn(Oa[f][2]*inv1, Oa[f][3]*inv1);
    }
}

// ---------------------------------------------------------------------------
extern "C" void kernel_launch(void* const* d_in, const int* in_sizes, int n_in,
                              void* d_out, int out_size)
{
    const float* q  = (const float*)d_in[0];
    const float* k  = (const float*)d_in[1];
    const float* v  = (const float*)d_in[2];
    // d_in[3] = mask (strict causal tril) — implemented analytically
    const float* Wq = (const float*)d_in[4];
    const float* bq = (const float*)d_in[5];
    const float* Wk = (const float*)d_in[6];
    const float* bk = (const float*)d_in[7];
    const float* Wv = (const float*)d_in[8];
    const float* bv = (const float*)d_in[9];
    const float* Wo = (const float*)d_in[10];
    const float* bo = (const float*)d_in[11];
    float* out = (float*)d_out;

    __half *pXh, *pWh, *pQh, *pKh, *pVh, *pVt, *pCtx;
    cudaGetSymbolAddress((void**)&pXh,  g_Xh);
    cudaGetSymbolAddress((void**)&pWh,  g_Wh);
    cudaGetSymbolAddress((void**)&pQh,  g_Qh);
    cudaGetSymbolAddress((void**)&pKh,  g_Kh);
    cudaGetSymbolAddress((void**)&pVh,  g_Vh);
    cudaGetSymbolAddress((void**)&pVt,  g_Vt);
    cudaGetSymbolAddress((void**)&pCtx, g_Ctx);

    cudaFuncSetAttribute(gemm_qkv, cudaFuncAttributeMaxDynamicSharedMemorySize, GSMEM_B);
    cudaFuncSetAttribute(gemm_out, cudaFuncAttributeMaxDynamicSharedMemorySize, GSMEM_B);
    cudaFuncSetAttribute(attn_tc,  cudaFuncAttributeMaxDynamicSharedMemorySize, AT_SMEM_B);

    // fp32 -> fp16 conversion
    prep_half3<<<dim3(MT*DD/(4*256), 1, 3), 256>>>(q, k, v, pXh);
    prep_half4<<<dim3(DD*DD/(4*256), 1, 4), 256>>>(Wq, Wk, Wv, Wo, pWh);

    // merged QKV projection
    gemm_qkv<<<dim3(DD/128, MT/128, 3), 256, GSMEM_B>>>(
        pXh, pWh, bq, bk, bv, pQh, pKh, pVh);

    // V transpose for PV mma operand layout
    transpose_v<<<dim3(SS/64, BB*HH), 256>>>(pVh, pVt);

    dim3 gAttn(BB*HH, SS/128);    // (32, 16), qt reversed inside
    attn_tc<<<gAttn, 256, AT_SMEM_B>>>(pQh, pKh, pVt, pCtx);

    gemm_out<<<dim3(DD/128, MT/128), 256, GSMEM_B>>>(pCtx, pWh + 3*(size_t)DD*DD, bo, out);
}

// round 15
// speedup vs baseline: 3.2835x; 1.0461x over previous
#include <cuda_runtime.h>
#include <cuda_fp16.h>
#include <mma.h>
#include <cstdint>

using namespace nvcuda;

// Problem constants
#define BB 2
#define SS 2048
#define DD 1024
#define HH 16
#define DK 64
#define MT (BB*SS)      // 4096 token rows

// Scratch (device globals — no allocation allowed)
__device__ __half g_Xh[3*MT*DD];        // fp16 q,k,v inputs
__device__ __half g_Wh[4*DD*DD];        // fp16 weights
__device__ __half g_Qh[BB*HH*SS*DK];    // [B,H,S,DK]
__device__ __half g_Kh[BB*HH*SS*DK];
__device__ __half g_Vt[BB*HH*DK*SS];    // [B,H,DK,S] transposed V (written by GEMM)
__device__ __half g_Ctx[BB*SS*DD];      // [B,S,D]

// ---------------------------------------------------------------------------
// helpers
// ---------------------------------------------------------------------------
__device__ __forceinline__ uint32_t smem_u32(const void* p) {
    uint32_t a;
    asm("{ .reg .u64 t; cvta.to.shared.u64 t, %1; cvt.u32.u64 %0, t; }"
        : "=r"(a) : "l"(p));
    return a;
}

__device__ __forceinline__ void mma16816(float c[4], const uint32_t a[4],
                                         uint32_t b0, uint32_t b1) {
    asm volatile(
        "mma.sync.aligned.m16n8k16.row.col.f32.f16.f16.f32 "
        "{%0,%1,%2,%3}, {%4,%5,%6,%7}, {%8,%9}, {%0,%1,%2,%3};"
        : "+f"(c[0]), "+f"(c[1]), "+f"(c[2]), "+f"(c[3])
        : "r"(a[0]), "r"(a[1]), "r"(a[2]), "r"(a[3]), "r"(b0), "r"(b1));
}

#define CP_ASYNC16(saddr, gptr) \
    asm volatile("cp.async.cg.shared.global [%0], [%1], 16;" \
                 :: "r"((uint32_t)(saddr)), "l"(gptr))
#define CP_COMMIT() asm volatile("cp.async.commit_group;" ::: "memory")
#define CP_WAIT(n)  asm volatile("cp.async.wait_group %0;" :: "n"(n) : "memory")

// ---------------------------------------------------------------------------
// Pre-pass: convert all 7 fp32 tensors to fp16 in ONE launch.
// z = 0..2 : q,k,v (MT*DD each, 4096 blocks)
// z = 3..6 : Wq,Wk,Wv,Wo (DD*DD each, first 1024 blocks active)
// ---------------------------------------------------------------------------
__global__ void prep_all(const float* __restrict__ q, const float* __restrict__ k,
                         const float* __restrict__ v,
                         const float* __restrict__ w0, const float* __restrict__ w1,
                         const float* __restrict__ w2, const float* __restrict__ w3,
                         __half* __restrict__ Xh, __half* __restrict__ Wh)
{
    const int z = blockIdx.z;
    const float* src;
    __half* d;
    if (z < 3) {
        src = (z == 0) ? q : (z == 1) ? k : v;
        d = Xh + (size_t)z * MT * DD;
    } else {
        if (blockIdx.x >= (DD*DD)/(4*256)) return;
        src = (z == 3) ? w0 : (z == 4) ? w1 : (z == 5) ? w2 : w3;
        d = Wh + (size_t)(z - 3) * DD * DD;
    }
    int i = blockIdx.x * 256 + threadIdx.x;
    float4 vv = *(const float4*)&src[(size_t)i * 4];
    *(__half2*)&d[(size_t)i*4 + 0] = __floats2half2_rn(vv.x, vv.y);
    *(__half2*)&d[(size_t)i*4 + 2] = __floats2half2_rn(vv.z, vv.w);
}

// ---------------------------------------------------------------------------
// wmma fp16 GEMM body: C[4096,1024] = A @ W + bias. A,W fp16, acc fp32.
// 128x128 CTA tile, BK=32, 8 warps (4x2 warp grid, 32x64 warp tiles).
// MODE 0: fp32 row-major.  MODE 1: fp16 head-split [B,H,S,DK].
// MODE 2: fp16 transposed head-split [B,H,DK,S]  (V path).
// ---------------------------------------------------------------------------
#define GBK 32
#define ALD 40    // A smem row stride (halfs)
#define BLD 136   // B smem row stride (halfs)
#define GA_STAGE (128*ALD)                       // halfs
#define GB_STAGE (GBK*BLD)                       // halfs
#define GSMEM_B  ((2*GA_STAGE + 2*GB_STAGE)*2)   // 37888 bytes

template<int MODE>
__device__ __forceinline__ void gemm_body(
    const __half* __restrict__ A, const __half* __restrict__ B,
    const float* __restrict__ bias, void* __restrict__ C)
{
    extern __shared__ __align__(128) __half smh[];
    __half* As = smh;                      // [2][128][40]
    __half* Bs = smh + 2 * GA_STAGE;       // [2][32][136]
    float* smf = (float*)smh;              // epilogue staging (64x136 fp32)
    const uint32_t sAs = smem_u32(As);
    const uint32_t sBs = smem_u32(Bs);

    const int tid = threadIdx.x;
    const int w  = tid >> 5;
    const int wr = w >> 1;            // 0..3 -> rows 32*wr
    const int wc = w & 1;             // 0..1 -> cols 64*wc
    const int row0 = blockIdx.y * 128;
    const int col0 = blockIdx.x * 128;

    wmma::fragment<wmma::accumulator, 16, 16, 16, float> acc[2][4];
    #pragma unroll
    for (int i = 0; i < 2; i++)
        #pragma unroll
        for (int j = 0; j < 4; j++) wmma::fill_fragment(acc[i][j], 0.f);

    auto loadA = [&](int ks, int buf) {
        const __half* Ag = A + (size_t)row0 * DD + ks * GBK;
        const uint32_t dst = sAs + buf * GA_STAGE * 2;
        #pragma unroll
        for (int u = 0; u < 2; u++) {
            int c = u * 256 + tid;             // 512 chunks of 8 halfs
            int r = c >> 2, ch = c & 3;
            CP_ASYNC16(dst + r * (ALD*2) + ch * 16, Ag + (size_t)r * DD + ch * 8);
        }
    };
    auto loadB = [&](int ks, int buf) {
        const __half* Bg = B + (size_t)(ks * GBK) * DD + col0;
        const uint32_t dst = sBs + buf * GB_STAGE * 2;
        #pragma unroll
        for (int u = 0; u < 2; u++) {
            int c = u * 256 + tid;             // 512 chunks
            int r = c >> 4, ch = c & 15;
            CP_ASYNC16(dst + r * (BLD*2) + ch * 16, Bg + (size_t)r * DD + ch * 8);
        }
    };

    loadA(0, 0); loadB(0, 0); CP_COMMIT();

    const int NK = DD / GBK;          // 32
    for (int ks = 0; ks < NK; ks++) {
        if (ks + 1 < NK) {
            loadA(ks + 1, (ks + 1) & 1);
            loadB(ks + 1, (ks + 1) & 1);
            CP_COMMIT();
            CP_WAIT(1);
        } else {
            CP_WAIT(0);
        }
        __syncthreads();

        const __half* Ab = As + (ks & 1) * GA_STAGE + wr * 32 * ALD;
        const __half* Bb = Bs + (ks & 1) * GB_STAGE + wc * 64;
        #pragma unroll
        for (int kk = 0; kk < 2; kk++) {      // BK/16
            wmma::fragment<wmma::matrix_a, 16, 16, 16, __half, wmma::row_major> fa[2];
            wmma::fragment<wmma::matrix_b, 16, 16, 16, __half, wmma::row_major> fb[4];
            #pragma unroll
            for (int im = 0; im < 2; im++)
                wmma::load_matrix_sync(fa[im], Ab + im * 16 * ALD + kk * 16, ALD);
            #pragma unroll
            for (int in = 0; in < 4; in++)
                wmma::load_matrix_sync(fb[in], Bb + kk * 16 * BLD + in * 16, BLD);
            #pragma unroll
            for (int im = 0; im < 2; im++)
                #pragma unroll
                for (int in = 0; in < 4; in++)
                    wmma::mma_sync(acc[im][in], fa[im], fb[in], acc[im][in]);
        }
        __syncthreads();
    }

    // Epilogue: two passes of 64 rows through fp32 smem staging (ld=136)
    #pragma unroll
    for (int p = 0; p < 2; p++) {
        if (wr >= p * 2 && wr < p * 2 + 2) {
            const int lr = (wr - p * 2) * 32;
            #pragma unroll
            for (int im = 0; im < 2; im++)
                #pragma unroll
                for (int in = 0; in < 4; in++)
                    wmma::store_matrix_sync(&smf[(lr + im*16) * 136 + wc*64 + in*16],
                                            acc[im][in], 136, wmma::mem_row_major);
        }
        __syncthreads();

        if (MODE == 2) {
            // V: write transposed [B,H,DK,S], coalesced along s.
            const int b  = row0 >> 11;
            const int s0 = (row0 & (SS - 1)) + p * 64;
            #pragma unroll
            for (int u = 0; u < 4; u++) {
                int id  = u * 256 + tid;            // 1024: col(128) x strip(8)
                int col = id >> 3;
                int r   = (id & 7) * 8;
                const int gcol = col0 + col;
                const int h  = gcol >> 6;
                const int dk = gcol & (DK - 1);
                const float bb = bias[gcol];
                __half hv[8];
                #pragma unroll
                for (int j = 0; j < 8; j++)
                    hv[j] = __float2half_rn(smf[(r + j) * 136 + col] + bb);
                __half* dst = (__half*)C + (((size_t)(b*HH + h))*DK + dk)*SS + s0 + r;
                *(uint4*)dst = *(uint4*)hv;
            }
        } else {
            #pragma unroll
            for (int u = 0; u < 8; u++) {
                int id = u * 256 + tid;                 // 2048 float4s
                int r  = id >> 5;
                int c4 = (id & 31) * 4;
                float4 vv = *(const float4*)&smf[r * 136 + c4];
                const int col = col0 + c4;
                vv.x += bias[col];   vv.y += bias[col+1];
                vv.z += bias[col+2]; vv.w += bias[col+3];
                const int trow = row0 + p * 64 + r;
                if (MODE == 0) {
                    *(float4*)&((float*)C)[(size_t)trow * DD + col] = vv;
                } else {
                    const int b = trow >> 11;
                    const int s = trow & (SS - 1);
                    const int h = col >> 6;
                    const int dk = col & (DK - 1);
                    __half* dst = (__half*)C + (((size_t)(b*HH + h))*SS + s)*DK + dk;
                    *(__half2*)&dst[0] = __floats2half2_rn(vv.x, vv.y);
                    *(__half2*)&dst[2] = __floats2half2_rn(vv.z, vv.w);
                }
            }
        }
        __syncthreads();
    }
}

// Merged QKV projection: grid (8, 32, 3). V goes out pre-transposed.
__global__ void __launch_bounds__(256)
gemm_qkv(const __half* __restrict__ Xh, const __half* __restrict__ Wh,
         const float* __restrict__ bq, const float* __restrict__ bk,
         const float* __restrict__ bv,
         __half* __restrict__ Qh, __half* __restrict__ Kh, __half* __restrict__ Vt)
{
    const int z = blockIdx.z;
    const __half* A = Xh + (size_t)z * MT * DD;
    const __half* B = Wh + (size_t)z * DD * DD;
    if (z == 0)      gemm_body<1>(A, B, bq, Qh);
    else if (z == 1) gemm_body<1>(A, B, bk, Kh);
    else             gemm_body<2>(A, B, bv, Vt);
}

__global__ void __launch_bounds__(256)
gemm_out(const __half* __restrict__ Ctx, const __half* __restrict__ Wh,
         const float* __restrict__ bo, float* __restrict__ C)
{
    gemm_body<0>(Ctx, Wh, bo, C);
}

// ---------------------------------------------------------------------------
// Flash attention, fp16 mma m16n8k16, P fully register-resident.
// CTA = (bh, 128-query tile), 8 warps x 16 query rows.
// K [key][dk] and V^T [dk][key] fp16 smem, double-buffered cp.async.
// ---------------------------------------------------------------------------
#define HPAD 72
#define AT_KS   (2*64*HPAD)                // halfs, one operand double-buffered
#define AT_SMEM_B (2*AT_KS*2)              // K + V, bytes = 36864

__global__ void __launch_bounds__(256, 2)
attn_tc(const __half* __restrict__ Qh, const __half* __restrict__ Kh,
        const __half* __restrict__ Vt, __half* __restrict__ Ctx)
{
    extern __shared__ __align__(128) __half smh[];
    __half* Ks = smh;                       // [2][64][72]  (key-major)
    __half* Vs = smh + AT_KS;               // [2][64][72]  (dk-major: V^T)
    const uint32_t sKs = smem_u32(Ks);
    const uint32_t sVs = smem_u32(Vs);

    const int bh = blockIdx.x;
    const int qt = (gridDim.y - 1) - blockIdx.y;    // big tiles first
    const int b  = bh >> 4;
    const int h  = bh & (HH - 1);

    const int tid  = threadIdx.x;
    const int w    = tid >> 5;
    const int lane = tid & 31;
    const int g    = lane >> 2;
    const int t    = lane & 3;
    const int r0   = w * 16;

    const __half* Qp = Qh + (size_t)bh * SS * DK + (size_t)qt * 128 * DK;
    const __half* Kp = Kh + (size_t)bh * SS * DK;
    const __half* Vp = Vt + (size_t)bh * DK * SS;

    // Q fragments straight from global (fp16 pairs)
    uint32_t qf[4][4];
    #pragma unroll
    for (int ks = 0; ks < 4; ks++) {
        const int k0 = ks * 16;
        qf[ks][0] = *(const uint32_t*)&Qp[(size_t)(r0+g  )*DK + k0 + 2*t    ];
        qf[ks][1] = *(const uint32_t*)&Qp[(size_t)(r0+g+8)*DK + k0 + 2*t    ];
        qf[ks][2] = *(const uint32_t*)&Qp[(size_t)(r0+g  )*DK + k0 + 2*t + 8];
        qf[ks][3] = *(const uint32_t*)&Qp[(size_t)(r0+g+8)*DK + k0 + 2*t + 8];
    }

    float m0 = -1e30f, m1 = -1e30f, l0 = 0.f, l1 = 0.f;
    float Oa[8][4];
    #pragma unroll
    for (int f = 0; f < 8; f++)
        #pragma unroll
        for (int r = 0; r < 4; r++) Oa[f][r] = 0.f;

    const int ktmax = 2 * qt + 1;
    const float SCL = 0.125f * 1.44269504088896f;   // 1/sqrt(dk) * log2(e)

    // K tile [64 keys][64 dk], V^T tile [64 dk][64 keys]
    auto load_kv = [&](int kt, int buf) {
        const uint32_t dK = sKs + buf * (64*HPAD*2);
        const uint32_t dV = sVs + buf * (64*HPAD*2);
        #pragma unroll
        for (int u = 0; u < 2; u++) {
            int c = u * 256 + tid;            // 512 chunks each of 8 halfs
            int row = c >> 3, ch = c & 7;
            CP_ASYNC16(dK + row*(HPAD*2) + ch*16,
                       Kp + (size_t)(kt*64 + row)*DK + ch*8);
            CP_ASYNC16(dV + row*(HPAD*2) + ch*16,
                       Vp + (size_t)row*SS + kt*64 + ch*8);
        }
        CP_COMMIT();
    };

    load_kv(0, 0);

    for (int kt = 0; kt <= ktmax; kt++) {
        CP_WAIT(0);
        __syncthreads();      // load(kt) visible; all warps done with other buffer
        if (kt + 1 <= ktmax) load_kv(kt + 1, (kt + 1) & 1);

        const __half* Kb = Ks + (kt & 1) * 64 * HPAD;
        const __half* Vb = Vs + (kt & 1) * 64 * HPAD;

        // S = Q @ K^T
        float Sa[8][4];
        #pragma unroll
        for (int f = 0; f < 8; f++)
            #pragma unroll
            for (int r = 0; r < 4; r++) Sa[f][r] = 0.f;
        #pragma unroll
        for (int ks = 0; ks < 4; ks++) {
            const int k0 = ks * 16;
            #pragma unroll
            for (int f = 0; f < 8; f++) {
                uint32_t b0 = *(const uint32_t*)&Kb[(f*8+g)*HPAD + k0 + 2*t    ];
                uint32_t b1 = *(const uint32_t*)&Kb[(f*8+g)*HPAD + k0 + 2*t + 8];
                mma16816(Sa[f], qf[ks], b0, b1);
            }
        }
        #pragma unroll
        for (int f = 0; f < 8; f++) {
            Sa[f][0] *= SCL; Sa[f][1] *= SCL; Sa[f][2] *= SCL; Sa[f][3] *= SCL;
        }

        // causal mask (near/on diagonal only)
        if (kt >= 2 * qt) {
            const int grow0 = qt*128 + r0 + g;
            const int grow1 = grow0 + 8;
            #pragma unroll
            for (int f = 0; f < 8; f++) {
                const int c0 = kt*64 + f*8 + 2*t;
                if (c0     > grow0) Sa[f][0] = -1e30f;
                if (c0 + 1 > grow0) Sa[f][1] = -1e30f;
                if (c0     > grow1) Sa[f][2] = -1e30f;
                if (c0 + 1 > grow1) Sa[f][3] = -1e30f;
            }
        }

        // online softmax (log2 domain)
        float mx0 = -1e30f, mx1 = -1e30f;
        #pragma unroll
        for (int f = 0; f < 8; f++) {
            mx0 = fmaxf(mx0, fmaxf(Sa[f][0], Sa[f][1]));
            mx1 = fmaxf(mx1, fmaxf(Sa[f][2], Sa[f][3]));
        }
        mx0 = fmaxf(mx0, __shfl_xor_sync(0xffffffffu, mx0, 1));
        mx0 = fmaxf(mx0, __shfl_xor_sync(0xffffffffu, mx0, 2));
        mx1 = fmaxf(mx1, __shfl_xor_sync(0xffffffffu, mx1, 1));
        mx1 = fmaxf(mx1, __shfl_xor_sync(0xffffffffu, mx1, 2));

        const float mn0 = fmaxf(m0, mx0), mn1 = fmaxf(m1, mx1);
        const float corr0 = exp2f(m0 - mn0), corr1 = exp2f(m1 - mn1);
        float s0 = 0.f, s1 = 0.f;
        uint32_t phl[8], phh[8];     // P fragments in registers (rows g / g+8)
        #pragma unroll
        for (int f = 0; f < 8; f++) {
            float p00 = exp2f(Sa[f][0] - mn0);
            float p01 = exp2f(Sa[f][1] - mn0);
            float p10 = exp2f(Sa[f][2] - mn1);
            float p11 = exp2f(Sa[f][3] - mn1);
            s0 += p00 + p01;  s1 += p10 + p11;
            __half2 h0 = __floats2half2_rn(p00, p01);
            __half2 h1 = __floats2half2_rn(p10, p11);
            phl[f] = *(uint32_t*)&h0;
            phh[f] = *(uint32_t*)&h1;
        }
        s0 += __shfl_xor_sync(0xffffffffu, s0, 1);
        s0 += __shfl_xor_sync(0xffffffffu, s0, 2);
        s1 += __shfl_xor_sync(0xffffffffu, s1, 1);
        s1 += __shfl_xor_sync(0xffffffffu, s1, 2);
        l0 = l0 * corr0 + s0;  m0 = mn0;
        l1 = l1 * corr1 + s1;  m1 = mn1;

        #pragma unroll
        for (int f = 0; f < 8; f++) {
            Oa[f][0] *= corr0; Oa[f][1] *= corr0;
            Oa[f][2] *= corr1; Oa[f][3] *= corr1;
        }

        // O += P @ V   (A = P from registers, B = V^T [dk][key])
        #pragma unroll
        for (int ks = 0; ks < 4; ks++) {
            const int k0 = ks * 16;
            uint32_t pa[4];
            pa[0] = phl[2*ks];
            pa[1] = phh[2*ks];
            pa[2] = phl[2*ks + 1];
            pa[3] = phh[2*ks + 1];
            #pragma unroll
            for (int f = 0; f < 8; f++) {
                uint32_t b0 = *(const uint32_t*)&Vb[(f*8+g)*HPAD + k0 + 2*t    ];
                uint32_t b1 = *(const uint32_t*)&Vb[(f*8+g)*HPAD + k0 + 2*t + 8];
                mma16816(Oa[f], pa, b0, b1);
            }
        }
        // no trailing sync: next iteration's __syncthreads (after CP_WAIT)
        // fences buffer reuse.
    }

    // normalize + write Ctx [B,S,D] fp16 (feeds final GEMM)
    const float inv0 = 1.f / l0, inv1 = 1.f / l1;
    const int srow0 = qt*128 + r0 + g;
    const int srow1 = srow0 + 8;
    #pragma unroll
    for (int f = 0; f < 8; f++) {
        const int col = h*64 + f*8 + 2*t;
        *(__half2*)&Ctx[((size_t)(b*SS + srow0))*DD + col] =
            __floats2half2_rn(Oa[f][0]*inv0, Oa[f][1]*inv0);
        *(__half2*)&Ctx[((size_t)(b*SS + srow1))*DD + col] =
            __floats2half2_rn(Oa[f][2]*inv1, Oa[f][3]*inv1);
    }
}

// ---------------------------------------------------------------------------
extern "C" void kernel_launch(void* const* d_in, const int* in_sizes, int n_in,
                              void* d_out, int out_size)
{
    const float* q  = (const float*)d_in[0];
    const float* k  = (const float*)d_in[1];
    const float* v  = (const float*)d_in[2];
    // d_in[3] = mask (strict causal tril) — implemented analytically
    const float* Wq = (const float*)d_in[4];
    const float* bq = (const float*)d_in[5];
    const float* Wk = (const float*)d_in[6];
    const float* bk = (const float*)d_in[7];
    const float* Wv = (const float*)d_in[8];
    const float* bv = (const float*)d_in[9];
    const float* Wo = (const float*)d_in[10];
    const float* bo = (const float*)d_in[11];
    float* out = (float*)d_out;

    __half *pXh, *pWh, *pQh, *pKh, *pVt, *pCtx;
    cudaGetSymbolAddress((void**)&pXh,  g_Xh);
    cudaGetSymbolAddress((void**)&pWh,  g_Wh);
    cudaGetSymbolAddress((void**)&pQh,  g_Qh);
    cudaGetSymbolAddress((void**)&pKh,  g_Kh);
    cudaGetSymbolAddress((void**)&pVt,  g_Vt);
    cudaGetSymbolAddress((void**)&pCtx, g_Ctx);

    cudaFuncSetAttribute(gemm_qkv, cudaFuncAttributeMaxDynamicSharedMemorySize, GSMEM_B);
    cudaFuncSetAttribute(gemm_out, cudaFuncAttributeMaxDynamicSharedMemorySize, GSMEM_B);
    cudaFuncSetAttribute(attn_tc,  cudaFuncAttributeMaxDynamicSharedMemorySize, AT_SMEM_B);

    // fp32 -> fp16 conversion (single launch)
    prep_all<<<dim3(MT*DD/(4*256), 1, 7), 256>>>(q, k, v, Wq, Wk, Wv, Wo, pXh, pWh);

    // merged QKV projection; V written pre-transposed
    gemm_qkv<<<dim3(DD/128, MT/128, 3), 256, GSMEM_B>>>(
        pXh, pWh, bq, bk, bv, pQh, pKh, pVt);

    dim3 gAttn(BB*HH, SS/128);    // (32, 16), qt reversed inside
    attn_tc<<<gAttn, 256, AT_SMEM_B>>>(pQh, pKh, pVt, pCtx);

    gemm_out<<<dim3(DD/128, MT/128), 256, GSMEM_B>>>(pCtx, pWh + 3*(size_t)DD*DD, bo, out);
}